// round 6
// baseline (speedup 1.0000x reference)
#include <cuda_runtime.h>
#include <math.h>
#include <stdint.h>

// Problem constants
#define BB   256
#define HS   512
#define G4   2048              // 4*HS
#define HEBB_PER_B (512*512)
#define NSPLIT 8               // split-K factor for the gates GEMM (k=128 each)

// Scratch (device globals; no runtime allocation allowed)
__device__ float g_part[NSPLIT * BB * G4];   // split-K partial gates (16 MB)
__device__ float g_mscalar[BB];              // tanh(h . nm_w + nm_b) per batch

__device__ __forceinline__ float sigmoidf_(float x) {
    return 1.0f / (1.0f + expf(-x));
}

__device__ __forceinline__ uint32_t f2tf32(float f) {
    uint32_t r;
    asm("cvt.rna.tf32.f32 %0, %1;" : "=r"(r) : "f"(f));
    return r;
}

__device__ __forceinline__ void mma_tf32(float& c0, float& c1, float& c2, float& c3,
                                         uint32_t a0, uint32_t a1, uint32_t a2, uint32_t a3,
                                         uint32_t b0, uint32_t b1) {
    asm volatile(
        "mma.sync.aligned.m16n8k8.row.col.f32.tf32.tf32.f32 "
        "{%0,%1,%2,%3}, {%4,%5,%6,%7}, {%8,%9}, {%0,%1,%2,%3};"
        : "+f"(c0), "+f"(c1), "+f"(c2), "+f"(c3)
        : "r"(a0), "r"(a1), "r"(a2), "r"(a3), "r"(b0), "r"(b1));
}

// ---------------------------------------------------------------------------
// Kernel 1: split-K gates GEMM on TENSOR CORES (tf32 mma.sync m16n8k8).
// gates = x @ W + h @ U (+ bias in split 0).  M=256, N=2048, K=1024.
// CTA: 64x64 tile, 256 thr = 8 warps (4 m x 2 n), warp tile 16x32.
// k-chunk 32, double-buffered SMEM, one barrier per chunk.
// A smem [k][m] rotated (m+8k)&63       -> conflict-free scalar frag loads.
// B smem [k][perm(n)] pad 72, perm(n) = (n&32)+(n&7)*4+((n>>3)&3)
//   -> the 4 B regs across a thread's n-tiles are ONE LDS.128 (conflict-free).
// Grid = 32 x 4 x 8 = 1024 CTAs.
// ---------------------------------------------------------------------------
__global__ void __launch_bounds__(256)
gemm_gates_kernel(const float* __restrict__ x,
                  const float* __restrict__ h,
                  const float* __restrict__ W,
                  const float* __restrict__ U,
                  const float* __restrict__ bias) {
    __shared__ __align__(16) uint32_t As[2][32][64];   // [buf][k][m rotated]
    __shared__ __align__(16) uint32_t Bs[2][32][72];   // [buf][k][perm(n)], pad 72

    const int tid  = threadIdx.x;        // 0..255
    const int lane = tid & 31;
    const int warp = tid >> 5;
    const int gid  = lane >> 2;          // 0..7
    const int tig  = lane & 3;           // 0..3
    const int wm   = (warp & 3) << 4;    // warp m offset 0..48
    const int wn   = (warp >> 2) << 5;   // warp n offset 0 or 32

    const int n0 = blockIdx.x * 64;
    const int m0 = blockIdx.y * 64;
    const int sp = blockIdx.z;           // K-split 0..7

    const float* Amat = (sp < 4) ? x : h;
    const float* Bmat = (sp < 4) ? W : U;
    const int kb = (sp & 3) * 128;

    // global load maps
    const int arow = tid >> 2;           // 0..63
    const int akc4 = (tid & 3) << 2;     // 0,4,8,12 (second chunk +16)
    const int bkr  = tid >> 3;           // 0..31
    const int bnc4 = (tid & 7) << 2;     // 0..28    (second chunk +32)

    const float* aptr = Amat + (m0 + arow) * 512 + kb + akc4;
    const float* bptr = Bmat + (size_t)(kb + bkr) * 2048 + n0 + bnc4;

    // permuted B store indices (n -> (n&32) + (n&7)*4 + ((n>>3)&3))
    const int bi_lo = ((bnc4 & 7) << 2) + ((bnc4 >> 3) & 3);   // for n = bnc4 + j : idx = bi_lo + 4j

    float acc[4][4] = {};                // [n-tile][reg]

    // prefetch chunk 0
    float4 aV0 = *(const float4*)(aptr);
    float4 aV1 = *(const float4*)(aptr + 16);
    float4 bV0 = *(const float4*)(bptr);
    float4 bV1 = *(const float4*)(bptr + 32);
    aptr += 32;
    bptr += (size_t)32 * 2048;

    #pragma unroll 1
    for (int chunk = 0; chunk < 4; ++chunk) {
        const int cur = chunk & 1;

        // --- STS A (transpose + rotate + tf32 cvt) ---
        {
            const float av0[4] = {aV0.x, aV0.y, aV0.z, aV0.w};
            const float av1[4] = {aV1.x, aV1.y, aV1.z, aV1.w};
            #pragma unroll
            for (int j = 0; j < 4; j++) {
                int k1 = akc4 + j;
                As[cur][k1][(arow + 8 * k1) & 63]             = f2tf32(av0[j]);
                As[cur][k1 + 16][(arow + 8 * (k1 + 16)) & 63] = f2tf32(av1[j]);
            }
        }
        // --- STS B (tf32 cvt, permuted scatter) ---
        {
            const float bv0[4] = {bV0.x, bV0.y, bV0.z, bV0.w};
            const float bv1[4] = {bV1.x, bV1.y, bV1.z, bV1.w};
            #pragma unroll
            for (int j = 0; j < 4; j++) {
                Bs[cur][bkr][bi_lo + 4 * j]      = f2tf32(bv0[j]);
                Bs[cur][bkr][32 + bi_lo + 4 * j] = f2tf32(bv1[j]);
            }
        }
        __syncthreads();

        // prefetch next chunk (overlaps mma)
        if (chunk < 3) {
            aV0 = *(const float4*)(aptr);
            aV1 = *(const float4*)(aptr + 16);
            bV0 = *(const float4*)(bptr);
            bV1 = *(const float4*)(bptr + 32);
            aptr += 32;
            bptr += (size_t)32 * 2048;
        }

        // --- compute: 4 k-steps of 8 ---
        #pragma unroll
        for (int ks = 0; ks < 32; ks += 8) {
            const int kA = ks + tig;
            const int kB = ks + tig + 4;
            uint32_t a0 = As[cur][kA][(wm + gid +     8 * kA) & 63];
            uint32_t a1 = As[cur][kA][(wm + gid + 8 + 8 * kA) & 63];
            uint32_t a2 = As[cur][kB][(wm + gid +     8 * kB) & 63];
            uint32_t a3 = As[cur][kB][(wm + gid + 8 + 8 * kB) & 63];
            uint4 bq0 = *(const uint4*)&Bs[cur][kA][wn + gid * 4];  // b0 for nt 0..3
            uint4 bq1 = *(const uint4*)&Bs[cur][kB][wn + gid * 4];  // b1 for nt 0..3
            mma_tf32(acc[0][0], acc[0][1], acc[0][2], acc[0][3], a0, a1, a2, a3, bq0.x, bq1.x);
            mma_tf32(acc[1][0], acc[1][1], acc[1][2], acc[1][3], a0, a1, a2, a3, bq0.y, bq1.y);
            mma_tf32(acc[2][0], acc[2][1], acc[2][2], acc[2][3], a0, a1, a2, a3, bq0.z, bq1.z);
            mma_tf32(acc[3][0], acc[3][1], acc[3][2], acc[3][3], a0, a1, a2, a3, bq0.w, bq1.w);
        }
    }

    // --- epilogue: write 64x64 accum to g_part[sp] (+ bias on split 0) ---
    float* outp = g_part + (size_t)sp * BB * G4;
    const int row0 = m0 + wm + gid;
    #pragma unroll
    for (int nt = 0; nt < 4; nt++) {
        const int col = n0 + wn + nt * 8 + 2 * tig;
        float b0 = 0.f, b1 = 0.f;
        if (sp == 0) { b0 = bias[col]; b1 = bias[col + 1]; }
        float2 d0 = make_float2(acc[nt][0] + b0, acc[nt][1] + b1);
        float2 d1 = make_float2(acc[nt][2] + b0, acc[nt][3] + b1);
        *(float2*)&outp[(size_t)row0 * 2048 + col]       = d0;
        *(float2*)&outp[(size_t)(row0 + 8) * 2048 + col] = d1;
    }
}

// ---------------------------------------------------------------------------
// Kernel 2: m_scalar[b] = tanh( dot(h[b,:], nm_w[0,:]) + nm_b[0] )   (NM == 1)
// ---------------------------------------------------------------------------
__global__ void mscalar_kernel(const float* __restrict__ h,
                               const float* __restrict__ nm_w,
                               const float* __restrict__ nm_b) {
    const int b = blockIdx.x;
    const int t = threadIdx.x;    // 128 threads
    float s = 0.0f;
    #pragma unroll
    for (int i = t; i < 512; i += 128) s += h[b * 512 + i] * nm_w[i];
    #pragma unroll
    for (int o = 16; o > 0; o >>= 1) s += __shfl_down_sync(0xffffffff, s, o);
    __shared__ float red[4];
    if ((t & 31) == 0) red[t >> 5] = s;
    __syncthreads();
    if (t == 0)
        g_mscalar[b] = tanhf(red[0] + red[1] + red[2] + red[3] + nm_b[0]);
}

// ---------------------------------------------------------------------------
// Kernel 3: fused strip kernel, strip held in REGISTERS, streaming hints.
// Grid (32 strips of 16 cols, 256 batches), 256 threads.
// hebb is read ONCE (ldcs) and hebb_new written once (stcs).
// ---------------------------------------------------------------------------
__global__ void __launch_bounds__(256)
hebb_kernel(const float* __restrict__ h_t,
            const float* __restrict__ c_t,
            const float* __restrict__ hebb,
            const float* __restrict__ alpha,
            const float* __restrict__ mt_w,
            const float* __restrict__ mt_b,
            float* __restrict__ out) {
    __shared__ float red[8][16];         // per-warp column partials
    __shared__ float gsm[NSPLIT][4][16]; // gate partials [sp][gate][k]
    __shared__ float a_s[16];            // m_t[k] * g_t[k]

    const int b  = blockIdx.y;
    const int k0 = blockIdx.x * 16;
    const int t  = threadIdx.x;        // 256
    const int c4 = t & 3;              // float4 column group
    const int r0 = t >> 2;             // base row 0..63
    const int lane = t & 31;
    const int wid  = t >> 5;

    const float* hebb_b = hebb + (size_t)b * HEBB_PER_B + k0 + c4 * 4;
    const float* hrow   = h_t + b * 512;

    // --- front: all global loads issued before any dependency stall ---
    float4 v[8];
    float hr[8];
    #pragma unroll
    for (int j = 0; j < 8; j++)
        v[j] = __ldcs((const float4*)(hebb_b + (size_t)(r0 + j * 64) * 512));
    #pragma unroll
    for (int j = 0; j < 8; j++)
        hr[j] = __ldg(hrow + r0 + j * 64);
    if (t < 16 * NSPLIT) {
        const int ki = t & 15;
        const int sp = t >> 4;
        const float* gb = g_part + (size_t)sp * BB * G4 + b * 2048 + k0 + ki;
        gsm[sp][0][ki] = gb[0];
        gsm[sp][1][ki] = gb[512];
        gsm[sp][2][ki] = gb[1024];
        gsm[sp][3][ki] = gb[1536];
    }

    // --- reduction: acc over this thread's 8 rows ---
    float a0 = 0.f, a1 = 0.f, a2 = 0.f, a3 = 0.f;
    #pragma unroll
    for (int j = 0; j < 8; j++) {
        a0 += hr[j] * v[j].x;
        a1 += hr[j] * v[j].y;
        a2 += hr[j] * v[j].z;
        a3 += hr[j] * v[j].w;
    }
    #pragma unroll
    for (int o = 16; o >= 4; o >>= 1) {
        a0 += __shfl_down_sync(0xffffffff, a0, o);
        a1 += __shfl_down_sync(0xffffffff, a1, o);
        a2 += __shfl_down_sync(0xffffffff, a2, o);
        a3 += __shfl_down_sync(0xffffffff, a3, o);
    }
    if (lane < 4) {
        red[wid][lane * 4 + 0] = a0;
        red[wid][lane * 4 + 1] = a1;
        red[wid][lane * 4 + 2] = a2;
        red[wid][lane * 4 + 3] = a3;
    }
    __syncthreads();

    // --- epilogue for the 16 owned k's (ALU + SMEM only) ---
    if (t < 16) {
        const int k = k0 + t;
        float s = red[0][t] + red[1][t] + red[2][t] + red[3][t]
                + red[4][t] + red[5][t] + red[6][t] + red[7][t];
        float ghebb = alpha[k] * s;

        float zi = 0.f, zf = 0.f, zg = 0.f, zo = 0.f;
        #pragma unroll
        for (int sp = 0; sp < NSPLIT; sp++) {
            zi += gsm[sp][0][t];
            zf += gsm[sp][1][t];
            zg += gsm[sp][2][t];
            zo += gsm[sp][3][t];
        }

        float gt = tanhf(zg + ghebb);
        float it = sigmoidf_(zi);
        float ft = sigmoidf_(zf);
        float ot = sigmoidf_(zo);

        float cn = ft * c_t[b * 512 + k] + it * gt;
        float hn = ot * tanhf(cn);

        out[b * 512 + k]           = hn;     // h_new
        out[BB * HS + b * 512 + k] = cn;     // c_new

        float mt = g_mscalar[b] * mt_w[k] + mt_b[k];
        a_s[t] = mt * gt;
    }
    __syncthreads();

    // --- store: update regs + write hebb_new (streaming stores) ---
    {
        float* outh = out + 2 * BB * HS + (size_t)b * HEBB_PER_B + k0 + c4 * 4;
        float4 av = *(const float4*)&a_s[c4 * 4];
        #pragma unroll
        for (int j = 0; j < 8; j++) {
            int i = r0 + j * 64;
            float hj = hr[j];
            float4 o;
            o.x = fminf(fmaxf(v[j].x + hj * av.x, -2.0f), 2.0f);
            o.y = fminf(fmaxf(v[j].y + hj * av.y, -2.0f), 2.0f);
            o.z = fminf(fmaxf(v[j].z + hj * av.z, -2.0f), 2.0f);
            o.w = fminf(fmaxf(v[j].w + hj * av.w, -2.0f), 2.0f);
            __stcs((float4*)(outh + (size_t)i * 512), o);
        }
    }
}

// ---------------------------------------------------------------------------
extern "C" void kernel_launch(void* const* d_in, const int* in_sizes, int n_in,
                              void* d_out, int out_size) {
    const float* x     = (const float*)d_in[0];
    const float* h     = (const float*)d_in[1];
    const float* c     = (const float*)d_in[2];
    const float* hebb  = (const float*)d_in[3];
    const float* W     = (const float*)d_in[4];
    const float* U     = (const float*)d_in[5];
    const float* bias  = (const float*)d_in[6];
    const float* alpha = (const float*)d_in[7];
    const float* nm_w  = (const float*)d_in[8];
    const float* nm_b  = (const float*)d_in[9];
    const float* mt_w  = (const float*)d_in[10];
    const float* mt_b  = (const float*)d_in[11];
    float* out = (float*)d_out;

    (void)in_sizes; (void)n_in; (void)out_size;

    gemm_gates_kernel<<<dim3(32, 4, NSPLIT), 256>>>(x, h, W, U, bias);
    mscalar_kernel<<<256, 128>>>(h, nm_w, nm_b);
    hebb_kernel<<<dim3(32, 256), 256>>>(h, c, hebb, alpha, mt_w, mt_b, out);
}

// round 7
// speedup vs baseline: 1.0066x; 1.0066x over previous
#include <cuda_runtime.h>
#include <math.h>
#include <stdint.h>

// Problem constants
#define BB   256
#define HS   512
#define G4   2048              // 4*HS
#define HEBB_PER_B (512*512)
#define NSPLIT 4               // split-K factor for the gates GEMM (k=256 each)

// Scratch (device globals; no runtime allocation allowed)
__device__ float g_part[NSPLIT * BB * G4];   // split-K partial gates (8 MB)
__device__ float g_mscalar[BB];              // tanh(h . nm_w + nm_b) per batch

__device__ __forceinline__ float sigmoidf_(float x) {
    return 1.0f / (1.0f + expf(-x));
}

__device__ __forceinline__ uint32_t f2tf32(float f) {
    uint32_t r;
    asm("cvt.rna.tf32.f32 %0, %1;" : "=r"(r) : "f"(f));
    return r;
}

__device__ __forceinline__ void mma_tf32(float& c0, float& c1, float& c2, float& c3,
                                         uint32_t a0, uint32_t a1, uint32_t a2, uint32_t a3,
                                         uint32_t b0, uint32_t b1) {
    asm volatile(
        "mma.sync.aligned.m16n8k8.row.col.f32.tf32.tf32.f32 "
        "{%0,%1,%2,%3}, {%4,%5,%6,%7}, {%8,%9}, {%0,%1,%2,%3};"
        : "+f"(c0), "+f"(c1), "+f"(c2), "+f"(c3)
        : "r"(a0), "r"(a1), "r"(a2), "r"(a3), "r"(b0), "r"(b1));
}

// ---------------------------------------------------------------------------
// Kernel 1: split-K gates GEMM on TENSOR CORES (tf32 mma.sync m16n8k8).
// gates = x @ W + h @ U (+ bias in split 0).  M=256, N=2048, K=1024.
// CTA: 64x64 tile, 128 thr = 4 warps (2m x 2n), warp tile 32x32
//   -> SMEM bytes per MMA cut 33% vs 16x32 warp tile (L1-wavefront bound).
// k-chunk 32, double-buffered SMEM, one barrier per chunk, 8 chunks.
// A smem [m][k] pad 36: STS.128 conflict-free, scalar frag loads
//   conflict-free (banks 4*gid+tig), zero index-rotation ALU.
// B smem [k][perm(n)] pad 72, perm(n)=(n&32)+(n&7)*4+((n>>3)&3):
//   4 B regs across n-tiles = ONE LDS.128 (R6-proven conflict-free).
// Grid = 32 x 4 x 4 = 512 CTAs.
// ---------------------------------------------------------------------------
__global__ void __launch_bounds__(128)
gemm_gates_kernel(const float* __restrict__ x,
                  const float* __restrict__ h,
                  const float* __restrict__ W,
                  const float* __restrict__ U,
                  const float* __restrict__ bias) {
    __shared__ __align__(16) uint32_t As[2][64][36];   // [buf][m][k] pad 36
    __shared__ __align__(16) uint32_t Bs[2][32][72];   // [buf][k][perm(n)] pad 72

    const int tid  = threadIdx.x;        // 0..127
    const int lane = tid & 31;
    const int warp = tid >> 5;           // 0..3
    const int gid  = lane >> 2;          // 0..7
    const int tig  = lane & 3;           // 0..3
    const int wm   = (warp & 1) << 5;    // warp m offset 0 or 32
    const int wn   = (warp >> 1) << 5;   // warp n offset 0 or 32

    const int n0 = blockIdx.x * 64;
    const int m0 = blockIdx.y * 64;
    const int sp = blockIdx.z;           // K-split 0..3

    const float* Amat = (sp < 2) ? x : h;
    const float* Bmat = (sp < 2) ? W : U;
    const int kb = (sp & 1) * 256;

    // A global/store map: thread -> row arow, k-half (16 wide), 4 float4
    const int arow  = tid >> 1;          // 0..63
    const int ahalf = (tid & 1) << 4;    // 0 or 16
    // B global/store map: thread -> row bkr, 4 float4 at n = bnc4 + 16j
    const int bkr  = tid >> 2;           // 0..31
    const int bnc4 = (tid & 3) << 2;     // 0,4,8,12

    const float* aptr = Amat + (m0 + arow) * 512 + kb + ahalf;
    const float* bptr = Bmat + (size_t)(kb + bkr) * 2048 + n0 + bnc4;

    float acc[2][4][4] = {};             // [m-tile][n-tile][reg]

    // prefetch chunk 0
    float4 aV[4], bV[4];
    #pragma unroll
    for (int j = 0; j < 4; j++) aV[j] = *(const float4*)(aptr + 4 * j);
    #pragma unroll
    for (int j = 0; j < 4; j++) bV[j] = *(const float4*)(bptr + 16 * j);
    aptr += 32;
    bptr += (size_t)32 * 2048;

    #pragma unroll 1
    for (int chunk = 0; chunk < 8; ++chunk) {
        const int cur = chunk & 1;

        // --- STS A: 4x STS.128, conflict-free ---
        #pragma unroll
        for (int j = 0; j < 4; j++) {
            uint4 p = make_uint4(f2tf32(aV[j].x), f2tf32(aV[j].y),
                                 f2tf32(aV[j].z), f2tf32(aV[j].w));
            *(uint4*)&As[cur][arow][ahalf + 4 * j] = p;
        }
        // --- STS B: permuted scatter (scalar) ---
        #pragma unroll
        for (int j = 0; j < 4; j++) {
            const float bv[4] = {bV[j].x, bV[j].y, bV[j].z, bV[j].w};
            #pragma unroll
            for (int e = 0; e < 4; e++) {
                int n = bnc4 + 16 * j + e;
                int w = (n & 32) + ((n & 7) << 2) + ((n >> 3) & 3);
                Bs[cur][bkr][w] = f2tf32(bv[e]);
            }
        }
        __syncthreads();

        // prefetch next chunk (overlaps mma)
        if (chunk < 7) {
            #pragma unroll
            for (int j = 0; j < 4; j++) aV[j] = *(const float4*)(aptr + 4 * j);
            #pragma unroll
            for (int j = 0; j < 4; j++) bV[j] = *(const float4*)(bptr + 16 * j);
            aptr += 32;
            bptr += (size_t)32 * 2048;
        }

        // --- compute: 4 k-steps of 8 ---
        #pragma unroll
        for (int ks = 0; ks < 32; ks += 8) {
            const int kA = ks + tig;
            const int kB = ks + tig + 4;
            uint4 bq0 = *(const uint4*)&Bs[cur][kA][wn + gid * 4];  // b0, nt 0..3
            uint4 bq1 = *(const uint4*)&Bs[cur][kB][wn + gid * 4];  // b1, nt 0..3
            #pragma unroll
            for (int mt = 0; mt < 2; mt++) {
                const int mb = wm + 16 * mt + gid;
                uint32_t a0 = As[cur][mb][kA];
                uint32_t a1 = As[cur][mb + 8][kA];
                uint32_t a2 = As[cur][mb][kB];
                uint32_t a3 = As[cur][mb + 8][kB];
                mma_tf32(acc[mt][0][0], acc[mt][0][1], acc[mt][0][2], acc[mt][0][3],
                         a0, a1, a2, a3, bq0.x, bq1.x);
                mma_tf32(acc[mt][1][0], acc[mt][1][1], acc[mt][1][2], acc[mt][1][3],
                         a0, a1, a2, a3, bq0.y, bq1.y);
                mma_tf32(acc[mt][2][0], acc[mt][2][1], acc[mt][2][2], acc[mt][2][3],
                         a0, a1, a2, a3, bq0.z, bq1.z);
                mma_tf32(acc[mt][3][0], acc[mt][3][1], acc[mt][3][2], acc[mt][3][3],
                         a0, a1, a2, a3, bq0.w, bq1.w);
            }
        }
    }

    // --- epilogue: write 64x64 accum to g_part[sp] (+ bias on split 0) ---
    float* outp = g_part + (size_t)sp * BB * G4;
    #pragma unroll
    for (int mt = 0; mt < 2; mt++) {
        const int row0 = m0 + wm + 16 * mt + gid;
        #pragma unroll
        for (int nt = 0; nt < 4; nt++) {
            const int col = n0 + wn + nt * 8 + 2 * tig;
            float b0 = 0.f, b1 = 0.f;
            if (sp == 0) { b0 = bias[col]; b1 = bias[col + 1]; }
            float2 d0 = make_float2(acc[mt][nt][0] + b0, acc[mt][nt][1] + b1);
            float2 d1 = make_float2(acc[mt][nt][2] + b0, acc[mt][nt][3] + b1);
            *(float2*)&outp[(size_t)row0 * 2048 + col]       = d0;
            *(float2*)&outp[(size_t)(row0 + 8) * 2048 + col] = d1;
        }
    }
}

// ---------------------------------------------------------------------------
// Kernel 2: m_scalar[b] = tanh( dot(h[b,:], nm_w[0,:]) + nm_b[0] )   (NM == 1)
// ---------------------------------------------------------------------------
__global__ void mscalar_kernel(const float* __restrict__ h,
                               const float* __restrict__ nm_w,
                               const float* __restrict__ nm_b) {
    const int b = blockIdx.x;
    const int t = threadIdx.x;    // 128 threads
    float s = 0.0f;
    #pragma unroll
    for (int i = t; i < 512; i += 128) s += h[b * 512 + i] * nm_w[i];
    #pragma unroll
    for (int o = 16; o > 0; o >>= 1) s += __shfl_down_sync(0xffffffff, s, o);
    __shared__ float red[4];
    if ((t & 31) == 0) red[t >> 5] = s;
    __syncthreads();
    if (t == 0)
        g_mscalar[b] = tanhf(red[0] + red[1] + red[2] + red[3] + nm_b[0]);
}

// ---------------------------------------------------------------------------
// Kernel 3: fused strip kernel, strip held in REGISTERS, streaming hints.
// Grid (32 strips of 16 cols, 256 batches), 256 threads.
// hebb is read ONCE (ldcs) and hebb_new written once (stcs).
// ---------------------------------------------------------------------------
__global__ void __launch_bounds__(256)
hebb_kernel(const float* __restrict__ h_t,
            const float* __restrict__ c_t,
            const float* __restrict__ hebb,
            const float* __restrict__ alpha,
            const float* __restrict__ mt_w,
            const float* __restrict__ mt_b,
            float* __restrict__ out) {
    __shared__ float red[8][16];         // per-warp column partials
    __shared__ float gsm[NSPLIT][4][16]; // gate partials [sp][gate][k]
    __shared__ float a_s[16];            // m_t[k] * g_t[k]

    const int b  = blockIdx.y;
    const int k0 = blockIdx.x * 16;
    const int t  = threadIdx.x;        // 256
    const int c4 = t & 3;              // float4 column group
    const int r0 = t >> 2;             // base row 0..63
    const int lane = t & 31;
    const int wid  = t >> 5;

    const float* hebb_b = hebb + (size_t)b * HEBB_PER_B + k0 + c4 * 4;
    const float* hrow   = h_t + b * 512;

    // --- front: all global loads issued before any dependency stall ---
    float4 v[8];
    float hr[8];
    #pragma unroll
    for (int j = 0; j < 8; j++)
        v[j] = __ldcs((const float4*)(hebb_b + (size_t)(r0 + j * 64) * 512));
    #pragma unroll
    for (int j = 0; j < 8; j++)
        hr[j] = __ldg(hrow + r0 + j * 64);
    if (t < 16 * NSPLIT) {
        const int ki = t & 15;
        const int sp = t >> 4;
        const float* gb = g_part + (size_t)sp * BB * G4 + b * 2048 + k0 + ki;
        gsm[sp][0][ki] = gb[0];
        gsm[sp][1][ki] = gb[512];
        gsm[sp][2][ki] = gb[1024];
        gsm[sp][3][ki] = gb[1536];
    }

    // --- reduction: acc over this thread's 8 rows ---
    float a0 = 0.f, a1 = 0.f, a2 = 0.f, a3 = 0.f;
    #pragma unroll
    for (int j = 0; j < 8; j++) {
        a0 += hr[j] * v[j].x;
        a1 += hr[j] * v[j].y;
        a2 += hr[j] * v[j].z;
        a3 += hr[j] * v[j].w;
    }
    #pragma unroll
    for (int o = 16; o >= 4; o >>= 1) {
        a0 += __shfl_down_sync(0xffffffff, a0, o);
        a1 += __shfl_down_sync(0xffffffff, a1, o);
        a2 += __shfl_down_sync(0xffffffff, a2, o);
        a3 += __shfl_down_sync(0xffffffff, a3, o);
    }
    if (lane < 4) {
        red[wid][lane * 4 + 0] = a0;
        red[wid][lane * 4 + 1] = a1;
        red[wid][lane * 4 + 2] = a2;
        red[wid][lane * 4 + 3] = a3;
    }
    __syncthreads();

    // --- epilogue for the 16 owned k's (ALU + SMEM only) ---
    if (t < 16) {
        const int k = k0 + t;
        float s = red[0][t] + red[1][t] + red[2][t] + red[3][t]
                + red[4][t] + red[5][t] + red[6][t] + red[7][t];
        float ghebb = alpha[k] * s;

        float zi = 0.f, zf = 0.f, zg = 0.f, zo = 0.f;
        #pragma unroll
        for (int sp = 0; sp < NSPLIT; sp++) {
            zi += gsm[sp][0][t];
            zf += gsm[sp][1][t];
            zg += gsm[sp][2][t];
            zo += gsm[sp][3][t];
        }

        float gt = tanhf(zg + ghebb);
        float it = sigmoidf_(zi);
        float ft = sigmoidf_(zf);
        float ot = sigmoidf_(zo);

        float cn = ft * c_t[b * 512 + k] + it * gt;
        float hn = ot * tanhf(cn);

        out[b * 512 + k]           = hn;     // h_new
        out[BB * HS + b * 512 + k] = cn;     // c_new

        float mt = g_mscalar[b] * mt_w[k] + mt_b[k];
        a_s[t] = mt * gt;
    }
    __syncthreads();

    // --- store: update regs + write hebb_new (streaming stores) ---
    {
        float* outh = out + 2 * BB * HS + (size_t)b * HEBB_PER_B + k0 + c4 * 4;
        float4 av = *(const float4*)&a_s[c4 * 4];
        #pragma unroll
        for (int j = 0; j < 8; j++) {
            int i = r0 + j * 64;
            float hj = hr[j];
            float4 o;
            o.x = fminf(fmaxf(v[j].x + hj * av.x, -2.0f), 2.0f);
            o.y = fminf(fmaxf(v[j].y + hj * av.y, -2.0f), 2.0f);
            o.z = fminf(fmaxf(v[j].z + hj * av.z, -2.0f), 2.0f);
            o.w = fminf(fmaxf(v[j].w + hj * av.w, -2.0f), 2.0f);
            __stcs((float4*)(outh + (size_t)i * 512), o);
        }
    }
}

// ---------------------------------------------------------------------------
extern "C" void kernel_launch(void* const* d_in, const int* in_sizes, int n_in,
                              void* d_out, int out_size) {
    const float* x     = (const float*)d_in[0];
    const float* h     = (const float*)d_in[1];
    const float* c     = (const float*)d_in[2];
    const float* hebb  = (const float*)d_in[3];
    const float* W     = (const float*)d_in[4];
    const float* U     = (const float*)d_in[5];
    const float* bias  = (const float*)d_in[6];
    const float* alpha = (const float*)d_in[7];
    const float* nm_w  = (const float*)d_in[8];
    const float* nm_b  = (const float*)d_in[9];
    const float* mt_w  = (const float*)d_in[10];
    const float* mt_b  = (const float*)d_in[11];
    float* out = (float*)d_out;

    (void)in_sizes; (void)n_in; (void)out_size;

    gemm_gates_kernel<<<dim3(32, 4, NSPLIT), 128>>>(x, h, W, U, bias);
    mscalar_kernel<<<256, 128>>>(h, nm_w, nm_b);
    hebb_kernel<<<dim3(32, 256), 256>>>(h, c, hebb, alpha, mt_w, mt_b, out);
}